// round 1
// baseline (speedup 1.0000x reference)
#include <cuda_runtime.h>
#include <cuda_bf16.h>

// ---------------------------------------------------------------------------
// RPN training loss (faithful port of the buggy reference):
//   gt_idx[i] = argmax_j IoU(anchor_i, gt_j)   (first-max wins ties)
//   label = 1 if gt_idx >= 1, 0 if gt_idx == 0 (integer vs float-threshold bug)
//   sel   = first min(num_pos,128) positives by anchor index, then negatives
//           by anchor index (spilling back into positives if negatives run out)
//   cls   = mean softmax-CE over 256 samples
//   reg   = mean over 256 of 2 * sum smoothL1(label * (pred - encode(anchor,gt)))
// ---------------------------------------------------------------------------

#define NMAX   (1 << 20)
#define CHUNK  256
#define NBMAX  (NMAX / CHUNK)   // 4096
#define MMAX   512
#define CAP    256

__device__ int g_gt_idx[NMAX];
__device__ int g_blk_pos[NBMAX];
__device__ int g_blk_neg[NBMAX];
__device__ int g_pos_off[NBMAX];
__device__ int g_neg_off[NBMAX];
__device__ int g_num_pos;
__device__ int g_num_neg;
__device__ int g_pos_list[CAP];
__device__ int g_neg_list[CAP];

// --------------------------------------------------------------------------
// K1: per-anchor argmax IoU over gt boxes + per-block pos/neg counts.
// Division is IEEE (__fdiv_rn, matching XLA) but only executed when the
// intersection is strictly positive: iou==0 can never beat best (init 0)
// under strict '>', which exactly matches jnp.argmax first-max semantics.
// --------------------------------------------------------------------------
__global__ void k_argmax(const float4* __restrict__ anchors,
                         const float4* __restrict__ gt,
                         int N, int M) {
    __shared__ float sgx1[MMAX], sgy1[MMAX], sgx2[MMAX], sgy2[MMAX], sga[MMAX];
    for (int j = threadIdx.x; j < M; j += blockDim.x) {
        float4 g = gt[j];
        sgx1[j] = g.x; sgy1[j] = g.y; sgx2[j] = g.z; sgy2[j] = g.w;
        sga[j]  = (g.z - g.x) * (g.w - g.y);
    }
    __syncthreads();

    int i = blockIdx.x * blockDim.x + threadIdx.x;
    int best = 0;
    if (i < N) {
        float4 a = anchors[i];
        float areaA = (a.z - a.x) * (a.w - a.y);
        float bestv = 0.0f;
        #pragma unroll 4
        for (int j = 0; j < M; ++j) {
            float lx = fmaxf(a.x, sgx1[j]);
            float ly = fmaxf(a.y, sgy1[j]);
            float rx = fminf(a.z, sgx2[j]);
            float ry = fminf(a.w, sgy2[j]);
            float w = rx - lx;
            float h = ry - ly;
            if (w > 0.0f && h > 0.0f) {
                float inter = w * h;
                float iou = __fdiv_rn(inter, areaA + sga[j] - inter);
                if (iou > bestv) { bestv = iou; best = j; }
            }
        }
        g_gt_idx[i] = best;
    }

    int is_pos = (i < N) && (best >= 1);
    int is_neg = (i < N) && (best == 0);
    int cp = __syncthreads_count(is_pos);
    int cn = __syncthreads_count(is_neg);
    if (threadIdx.x == 0) {
        g_blk_pos[blockIdx.x] = cp;
        g_blk_neg[blockIdx.x] = cn;
    }
}

// --------------------------------------------------------------------------
// K2: single-block exclusive scan over per-chunk counts -> chunk offsets,
// totals, and list init.
// --------------------------------------------------------------------------
__global__ void k_scan(int nb) {
    __shared__ int sp[256], sn[256];
    int t = threadIdx.x;
    int per = (nb + 255) / 256;
    int base = t * per;
    int sump = 0, sumn = 0;
    for (int k = 0; k < per; ++k) {
        int idx = base + k;
        if (idx < nb) { sump += g_blk_pos[idx]; sumn += g_blk_neg[idx]; }
    }
    sp[t] = sump; sn[t] = sumn;
    __syncthreads();
    // Hillis-Steele inclusive scan over 256 per-thread sums
    for (int off = 1; off < 256; off <<= 1) {
        int vp = (t >= off) ? sp[t - off] : 0;
        int vn = (t >= off) ? sn[t - off] : 0;
        __syncthreads();
        sp[t] += vp; sn[t] += vn;
        __syncthreads();
    }
    int rp = (t == 0) ? 0 : sp[t - 1];
    int rn = (t == 0) ? 0 : sn[t - 1];
    for (int k = 0; k < per; ++k) {
        int idx = base + k;
        if (idx < nb) {
            g_pos_off[idx] = rp;
            g_neg_off[idx] = rn;
            rp += g_blk_pos[idx];
            rn += g_blk_neg[idx];
        }
    }
    if (t == 255) { g_num_pos = sp[255]; g_num_neg = sn[255]; }
    if (t < CAP) { g_pos_list[t] = 0; g_neg_list[t] = 0; }
}

// --------------------------------------------------------------------------
// K3: scatter the first CAP positive / negative anchor indices (in ascending
// anchor-index order) into g_pos_list / g_neg_list. Blocks whose offsets are
// already past CAP exit immediately.
// --------------------------------------------------------------------------
__global__ void k_select(int N) {
    int b = blockIdx.x;
    int po = g_pos_off[b];
    int no = g_neg_off[b];
    if (po >= CAP && no >= CAP) return;

    int i = b * CHUNK + threadIdx.x;
    int gi = (i < N) ? g_gt_idx[i] : -1;
    int is_pos = (gi >= 1);
    int is_neg = (gi == 0);

    unsigned bp = __ballot_sync(0xffffffffu, is_pos);
    unsigned bn = __ballot_sync(0xffffffffu, is_neg);
    int lane = threadIdx.x & 31;
    int warp = threadIdx.x >> 5;
    __shared__ int wp[8], wn[8];
    if (lane == 0) { wp[warp] = __popc(bp); wn[warp] = __popc(bn); }
    __syncthreads();
    int basep = 0, basen = 0;
    for (int w = 0; w < warp; ++w) { basep += wp[w]; basen += wn[w]; }
    unsigned ltmask = (1u << lane) - 1u;
    if (is_pos) {
        int r = po + basep + __popc(bp & ltmask);
        if (r < CAP) g_pos_list[r] = i;
    }
    if (is_neg) {
        int r = no + basen + __popc(bn & ltmask);
        if (r < CAP) g_neg_list[r] = i;
    }
}

// --------------------------------------------------------------------------
// K4: one block of 256 threads (one per sample) computes both losses.
// --------------------------------------------------------------------------
__global__ void k_loss(const float2* __restrict__ score,
                       const float4* __restrict__ pred,
                       const float4* __restrict__ anchors,
                       const float4* __restrict__ gt,
                       float* __restrict__ out) {
    int t = threadIdx.x;
    int num_pos = g_num_pos;
    int num_neg = g_num_neg;
    int cur_pos = min(num_pos, 128);

    int a, label;
    if (t < cur_pos) {
        a = g_pos_list[t];
        label = 1;
    } else {
        int j = t - cur_pos;
        if (j < num_neg) {
            a = g_neg_list[min(j, CAP - 1)];
            label = 0;
        } else {
            // reference's stable neg_order spills into positives in index order
            a = g_pos_list[min(j - num_neg, CAP - 1)];
            label = 1;
        }
    }

    // classification: -log_softmax(score[a])[label]
    float2 s = score[a];
    float m = fmaxf(s.x, s.y);
    float lse = m + logf(expf(s.x - m) + expf(s.y - m));
    float sl = label ? s.y : s.x;
    float cls = lse - sl;

    // regression: smooth-L1 on encoded target, zeroed for negatives
    float4 ab = anchors[a];
    int gi = g_gt_idx[a];
    float4 gb = gt[gi];
    float aw = ab.z - ab.x, ah = ab.w - ab.y;
    float acx = ab.x + 0.5f * aw, acy = ab.y + 0.5f * ah;
    float gw = gb.z - gb.x, gh = gb.w - gb.y;
    float gcx = gb.x + 0.5f * gw, gcy = gb.y + 0.5f * gh;
    float t0 = (gcx - acx) / aw;
    float t1 = (gcy - acy) / ah;
    float t2 = logf(gw / aw);
    float t3 = logf(gh / ah);
    float4 p = pred[a];
    float fl = (float)label;
    float d0 = fl * (p.x - t0);
    float d1 = fl * (p.y - t1);
    float d2 = fl * (p.z - t2);
    float d3 = fl * (p.w - t3);
    float ad0 = fabsf(d0), ad1 = fabsf(d1), ad2 = fabsf(d2), ad3 = fabsf(d3);
    float s0 = (ad0 < 1.0f) ? 0.5f * d0 * d0 : ad0 - 0.5f;
    float s1 = (ad1 < 1.0f) ? 0.5f * d1 * d1 : ad1 - 0.5f;
    float s2 = (ad2 < 1.0f) ? 0.5f * d2 * d2 : ad2 - 0.5f;
    float s3 = (ad3 < 1.0f) ? 0.5f * d3 * d3 : ad3 - 0.5f;
    float reg = 2.0f * (s0 + s1 + s2 + s3);

    __shared__ float rc[256], rr[256];
    rc[t] = cls;
    rr[t] = reg;
    __syncthreads();
    for (int off = 128; off > 0; off >>= 1) {
        if (t < off) { rc[t] += rc[t + off]; rr[t] += rr[t + off]; }
        __syncthreads();
    }
    if (t == 0) {
        out[0] = rc[0] * (1.0f / 256.0f);   // CLS_W = 1.0
        out[1] = rr[0] * (1.0f / 256.0f);
    }
}

extern "C" void kernel_launch(void* const* d_in, const int* in_sizes, int n_in,
                              void* d_out, int out_size) {
    const float2* score   = (const float2*)d_in[0];   // [N,2]
    const float4* pred    = (const float4*)d_in[1];   // [N,4]
    const float4* anchors = (const float4*)d_in[2];   // [N,4]
    const float4* gt      = (const float4*)d_in[3];   // [M,4]
    float* out = (float*)d_out;

    int N = in_sizes[2] / 4;
    int M = in_sizes[3] / 4;
    int nb = (N + CHUNK - 1) / CHUNK;

    k_argmax<<<nb, CHUNK>>>(anchors, gt, N, M);
    k_scan<<<1, 256>>>(nb);
    k_select<<<nb, CHUNK>>>(N);
    k_loss<<<1, 256>>>(score, pred, anchors, gt, out);
}